// round 14
// baseline (speedup 1.0000x reference)
#include <cuda_runtime.h>
#include <cuda_bf16.h>

// 1 CTA per 64x64 image, 256 threads, single launch.
// Thread t: col quad q=t&15 (cols 4q..4q+3), rows 4*(t>>4)..+3.
// ALL 18 loads (6 vec rows + 12 scalar halos) front-issued (MLP=18); window rows
// are direct register references -- NO shuffles, no expand step.
// Per-warp coeffs (lanes 0-8 load+clamp, shfl broadcast), hidden under loads.
// |gx|+|gy| == max(|conv(S)|, |conv(D)|), S=wr+wr^T, D=wr-wr^T.
// Warp min/max via redux.sync.u32 on float bits (g >= 0); cross-warp via smem atomics.

#define FULL 0xffffffffu
#define NUM_IMG 2048

__global__ __launch_bounds__(256)
void sobel_norm_kernel(const float* __restrict__ in,
                       const float* __restrict__ w,
                       const float* __restrict__ wf,
                       const float* __restrict__ scale_p,
                       float* __restrict__ out) {
    __shared__ unsigned s_mn, s_mx;

    const int tid  = threadIdx.x;
    const int lane = tid & 31;
    const int q    = tid & 15;        // col quad 0..15
    const int r0   = (tid >> 4) << 2; // first output row (0..60)
    const int c0   = q << 2;

    if (tid == 0) { s_mn = 0x7f800000u; s_mx = 0u; }
    __syncthreads();   // top-of-kernel: all warps arrive together, cheap

    const float* __restrict__ base = in + (size_t)blockIdx.x * 4096 + (r0 << 6) + c0;

    const bool pl = (q != 0);
    const bool pr = (q != 15);
    const bool tv = (r0 != 0);
    const bool bv = (r0 != 60);

    // ---- Front-issue ALL loads: 6 vec rows + 12 scalar halos (MLP=18) ----
    const float4 Z4 = make_float4(0.f, 0.f, 0.f, 0.f);
    const float4 m0 = tv ? *reinterpret_cast<const float4*>(base - 64)  : Z4;
    const float4 m1 =      *reinterpret_cast<const float4*>(base);
    const float4 m2 =      *reinterpret_cast<const float4*>(base + 64);
    const float4 m3 =      *reinterpret_cast<const float4*>(base + 128);
    const float4 m4 =      *reinterpret_cast<const float4*>(base + 192);
    const float4 m5 = bv ? *reinterpret_cast<const float4*>(base + 256) : Z4;

    const float l0 = (pl && tv) ? base[-65]  : 0.f;
    const float h0 = (pr && tv) ? base[-60]  : 0.f;
    const float l1 = pl ? base[-1]   : 0.f;
    const float h1 = pr ? base[4]    : 0.f;
    const float l2 = pl ? base[63]   : 0.f;
    const float h2 = pr ? base[68]   : 0.f;
    const float l3 = pl ? base[127]  : 0.f;
    const float h3 = pr ? base[132]  : 0.f;
    const float l4 = pl ? base[191]  : 0.f;
    const float h4 = pr ? base[196]  : 0.f;
    const float l5 = (pl && bv) ? base[255] : 0.f;
    const float h5 = (pr && bv) ? base[260] : 0.f;

    // ---- Per-warp coefficients (no barrier), hidden under loads ----
    float wv = 0.f;
    if (lane < 9) {
        const float f = fminf(fmaxf(__ldg(wf), 1.0f), 255.0f);
        wv = fminf(fmaxf(__ldg(w + lane), -1.0f), 1.0f) * f;
    }
    const float w0 = __shfl_sync(FULL, wv, 0);
    const float w1 = __shfl_sync(FULL, wv, 1);
    const float w2 = __shfl_sync(FULL, wv, 2);
    const float w3 = __shfl_sync(FULL, wv, 3);
    const float w4 = __shfl_sync(FULL, wv, 4);
    const float w5 = __shfl_sync(FULL, wv, 5);
    const float w6 = __shfl_sync(FULL, wv, 6);
    const float w7 = __shfl_sync(FULL, wv, 7);
    const float w8 = __shfl_sync(FULL, wv, 8);

    const float s00 = w0 + w0, s11 = w4 + w4, s22 = w8 + w8;
    const float s01 = w1 + w3, s02 = w2 + w6, s12 = w5 + w7;
    const float d01 = w1 - w3, d02 = w2 - w6, d12 = w5 - w7;

    // ---- Window rows as pure register arrays (compile-away) ----
    const float R0[6] = { l0, m0.x, m0.y, m0.z, m0.w, h0 };
    const float R1[6] = { l1, m1.x, m1.y, m1.z, m1.w, h1 };
    const float R2[6] = { l2, m2.x, m2.y, m2.z, m2.w, h2 };
    const float R3[6] = { l3, m3.x, m3.y, m3.z, m3.w, h3 };
    const float R4[6] = { l4, m4.x, m4.y, m4.z, m4.w, h4 };
    const float R5[6] = { l5, m5.x, m5.y, m5.z, m5.w, h5 };

    float g[16];
    float gmn = 3.4e38f;
    float gmx = 0.0f;   // g >= 0

    auto conv4 = [&](const float* a, const float* b, const float* c, float* go) {
#pragma unroll
        for (int p = 0; p < 4; p++) {
            const float a0 = a[p], a1 = a[p + 1], a2 = a[p + 2];
            const float b0 = b[p], b1 = b[p + 1], b2 = b[p + 2];
            const float c1 = c[p], c2 = c[p + 1], c3 = c[p + 2];
            float S = s00 * a0;
            S = fmaf(s11, b1, S);
            S = fmaf(s22, c3, S);
            S = fmaf(s01, a1 + b0, S);
            S = fmaf(s02, a2 + c1, S);
            S = fmaf(s12, b2 + c2, S);
            float D = d01 * (a1 - b0);
            D = fmaf(d02, a2 - c1, D);
            D = fmaf(d12, b2 - c2, D);
            const float gv = fmaxf(fabsf(S), fabsf(D));
            go[p] = gv;
            gmn = fminf(gmn, gv);
            gmx = fmaxf(gmx, gv);
        }
    };

    conv4(R0, R1, R2, g + 0);
    conv4(R1, R2, R3, g + 4);
    conv4(R2, R3, R4, g + 8);
    conv4(R3, R4, R5, g + 12);

    // --- warp reduction: integer redux on float bits (all g >= 0) ---
    unsigned wmn_u, wmx_u;
    asm("redux.sync.min.u32 %0, %1, 0xffffffff;" : "=r"(wmn_u) : "r"(__float_as_uint(gmn)));
    asm("redux.sync.max.u32 %0, %1, 0xffffffff;" : "=r"(wmx_u) : "r"(__float_as_uint(gmx)));
    if (lane == 0) {
        atomicMin(&s_mn, wmn_u);
        atomicMax(&s_mx, wmx_u);
    }
    __syncthreads();

    gmn = __uint_as_float(s_mn);   // broadcast LDS
    gmx = __uint_as_float(s_mx);

    const float mul = 255.0f / fmaxf(gmx - gmn, 1.0f);
    const float nb  = -gmn * mul;
    const float sc  = __ldg(scale_p);   // uniform broadcast

    // --- normalize + floor (+scale); float4 stores ---
    float* __restrict__ op = out + (size_t)blockIdx.x * 4096 + (r0 << 6) + c0;
    if (sc == 1.0f) {
#pragma unroll
        for (int i = 0; i < 4; i++) {
            float4 o4;
            o4.x = floorf(fmaf(g[i * 4 + 0], mul, nb));
            o4.y = floorf(fmaf(g[i * 4 + 1], mul, nb));
            o4.z = floorf(fmaf(g[i * 4 + 2], mul, nb));
            o4.w = floorf(fmaf(g[i * 4 + 3], mul, nb));
            *reinterpret_cast<float4*>(op + (i << 6)) = o4;
        }
    } else {
        const float isc = 1.0f / sc;
#pragma unroll
        for (int i = 0; i < 4; i++) {
            float4 o4;
            o4.x = floorf(fmaf(g[i * 4 + 0], mul, nb)) * isc;
            o4.y = floorf(fmaf(g[i * 4 + 1], mul, nb)) * isc;
            o4.z = floorf(fmaf(g[i * 4 + 2], mul, nb)) * isc;
            o4.w = floorf(fmaf(g[i * 4 + 3], mul, nb)) * isc;
            *reinterpret_cast<float4*>(op + (i << 6)) = o4;
        }
    }
}

extern "C" void kernel_launch(void* const* d_in, const int* in_sizes, int n_in,
                              void* d_out, int out_size) {
    const float* in      = (const float*)d_in[0];  // (2048,1,64,64) fp32
    const float* w       = (const float*)d_in[1];  // (1,9) fp32
    const float* wf      = (const float*)d_in[2];  // (1,) fp32
    const float* scale_p = (const float*)d_in[3];  // (1,1) fp32
    float* out = (float*)d_out;                    // (1,2048,1,64,64) fp32
    (void)in_sizes; (void)n_in; (void)out_size;

    sobel_norm_kernel<<<NUM_IMG, 256>>>(in, w, wf, scale_p, out);
}

// round 15
// speedup vs baseline: 1.1425x; 1.1425x over previous
#include <cuda_runtime.h>
#include <cuda_bf16.h>

// PERSISTENT kernel: grid = 740 CTAs (148 SMs x 5 resident), 256 threads.
// Each CTA loops over images blockIdx.x, +740, ... (2-3 images), so conv
// coefficients + setup are computed ONCE per CTA and there are no wave
// transitions. Inner body = R12 champion: LDG.128 rows front-issued, halo via
// warp shuffle, S/D conv split, redux.sync.u32 warp reduction, smem-atomic
// cross-warp combine. Reduction cells ping-pong on image parity so the
// re-init of parity p (after barrier B of image i) is ordered before image
// i+2's atomics by the intervening barriers.
// |gx|+|gy| == max(|conv(S)|, |conv(D)|), S=wr+wr^T, D=wr-wr^T. g >= 0.

#define FULL 0xffffffffu
#define NUM_IMG 2048
#define GRID 740

__global__ __launch_bounds__(256, 5)
void sobel_norm_kernel(const float* __restrict__ in,
                       const float* __restrict__ w,
                       const float* __restrict__ wf,
                       const float* __restrict__ scale_p,
                       float* __restrict__ out) {
    __shared__ unsigned cells[4];   // parity 0: [0]=min,[1]=max; parity 1: [2],[3]

    const int tid  = threadIdx.x;
    const int lane = tid & 31;
    const int q    = tid & 15;        // col quad 0..15
    const int r0   = (tid >> 4) << 2; // first output row (0..60)
    const int c0   = q << 2;
    const size_t off = (size_t)(r0 << 6) + c0;

    if (tid == 0) {
        cells[0] = 0x7f800000u; cells[1] = 0u;
        cells[2] = 0x7f800000u; cells[3] = 0u;
    }

    // ---- Per-warp coefficients: ONCE per CTA ----
    float wv = 0.f;
    if (lane < 9) {
        const float f = fminf(fmaxf(__ldg(wf), 1.0f), 255.0f);
        wv = fminf(fmaxf(__ldg(w + lane), -1.0f), 1.0f) * f;
    }
    const float w0 = __shfl_sync(FULL, wv, 0);
    const float w1 = __shfl_sync(FULL, wv, 1);
    const float w2 = __shfl_sync(FULL, wv, 2);
    const float w3 = __shfl_sync(FULL, wv, 3);
    const float w4 = __shfl_sync(FULL, wv, 4);
    const float w5 = __shfl_sync(FULL, wv, 5);
    const float w6 = __shfl_sync(FULL, wv, 6);
    const float w7 = __shfl_sync(FULL, wv, 7);
    const float w8 = __shfl_sync(FULL, wv, 8);

    const float s00 = w0 + w0, s11 = w4 + w4, s22 = w8 + w8;
    const float s01 = w1 + w3, s02 = w2 + w6, s12 = w5 + w7;
    const float d01 = w1 - w3, d02 = w2 - w6, d12 = w5 - w7;
    const float sc  = __ldg(scale_p);

    __syncthreads();   // orders cells init before first atomics

    auto expand = [&](float4 m, float* V) {
        float lf = __shfl_up_sync(FULL, m.w, 1);
        float rg = __shfl_down_sync(FULL, m.x, 1);
        if (q == 0)  lf = 0.f;
        if (q == 15) rg = 0.f;
        V[0] = lf;
        V[1] = m.x; V[2] = m.y; V[3] = m.z; V[4] = m.w;
        V[5] = rg;
    };

    int par = 0;
    for (int img = blockIdx.x; img < NUM_IMG; img += GRID, par ^= 1) {
        const float* __restrict__ base = in + (size_t)img * 4096 + off;

        // ---- Front-issue ALL 6 row loads (MLP=6) ----
        const float4 Z4 = make_float4(0.f, 0.f, 0.f, 0.f);
        const float4 mA = (r0 != 0)  ? *reinterpret_cast<const float4*>(base - 64)  : Z4;
        const float4 mB =              *reinterpret_cast<const float4*>(base);
        const float4 mC =              *reinterpret_cast<const float4*>(base + 64);
        const float4 mD =              *reinterpret_cast<const float4*>(base + 128);
        const float4 mE =              *reinterpret_cast<const float4*>(base + 192);
        const float4 mF = (r0 != 60) ? *reinterpret_cast<const float4*>(base + 256) : Z4;

        float g[16];
        float gmn = 3.4e38f;
        float gmx = 0.0f;   // g >= 0
        float W[3][6];

        auto conv4 = [&](const float* a, const float* b, const float* c, float* go) {
#pragma unroll
            for (int p = 0; p < 4; p++) {
                const float a0 = a[p], a1 = a[p + 1], a2 = a[p + 2];
                const float b0 = b[p], b1 = b[p + 1], b2 = b[p + 2];
                const float c1 = c[p], c2 = c[p + 1], c3 = c[p + 2];
                float S = s00 * a0;
                S = fmaf(s11, b1, S);
                S = fmaf(s22, c3, S);
                S = fmaf(s01, a1 + b0, S);
                S = fmaf(s02, a2 + c1, S);
                S = fmaf(s12, b2 + c2, S);
                float D = d01 * (a1 - b0);
                D = fmaf(d02, a2 - c1, D);
                D = fmaf(d12, b2 - c2, D);
                const float gv = fmaxf(fabsf(S), fabsf(D));
                go[p] = gv;
                gmn = fminf(gmn, gv);
                gmx = fmaxf(gmx, gv);
            }
        };

        expand(mA, W[0]);
        expand(mB, W[1]);
        expand(mC, W[2]);
        conv4(W[0], W[1], W[2], g + 0);

        expand(mD, W[0]);
        conv4(W[1], W[2], W[0], g + 4);

        expand(mE, W[1]);
        conv4(W[2], W[0], W[1], g + 8);

        expand(mF, W[2]);
        conv4(W[0], W[1], W[2], g + 12);

        // ---- warp reduction: integer redux on float bits (all g >= 0) ----
        unsigned wmn_u, wmx_u;
        asm("redux.sync.min.u32 %0, %1, 0xffffffff;" : "=r"(wmn_u) : "r"(__float_as_uint(gmn)));
        asm("redux.sync.max.u32 %0, %1, 0xffffffff;" : "=r"(wmx_u) : "r"(__float_as_uint(gmx)));
        const int cm = par << 1;
        if (lane == 0) {
            atomicMin(&cells[cm],     wmn_u);
            atomicMax(&cells[cm + 1], wmx_u);
        }
        __syncthreads();   // A: atomics complete

        gmn = __uint_as_float(cells[cm]);
        gmx = __uint_as_float(cells[cm + 1]);
        __syncthreads();   // B: all reads complete

        if (tid == 0) {    // re-init this parity; ordered before its next use
            cells[cm]     = 0x7f800000u;
            cells[cm + 1] = 0u;
        }

        const float mul = 255.0f / fmaxf(gmx - gmn, 1.0f);
        const float nb  = -gmn * mul;

        float* __restrict__ op = out + (size_t)img * 4096 + off;
        if (sc == 1.0f) {
#pragma unroll
            for (int i = 0; i < 4; i++) {
                float4 o4;
                o4.x = floorf(fmaf(g[i * 4 + 0], mul, nb));
                o4.y = floorf(fmaf(g[i * 4 + 1], mul, nb));
                o4.z = floorf(fmaf(g[i * 4 + 2], mul, nb));
                o4.w = floorf(fmaf(g[i * 4 + 3], mul, nb));
                *reinterpret_cast<float4*>(op + (i << 6)) = o4;
            }
        } else {
            const float isc = 1.0f / sc;
#pragma unroll
            for (int i = 0; i < 4; i++) {
                float4 o4;
                o4.x = floorf(fmaf(g[i * 4 + 0], mul, nb)) * isc;
                o4.y = floorf(fmaf(g[i * 4 + 1], mul, nb)) * isc;
                o4.z = floorf(fmaf(g[i * 4 + 2], mul, nb)) * isc;
                o4.w = floorf(fmaf(g[i * 4 + 3], mul, nb)) * isc;
                *reinterpret_cast<float4*>(op + (i << 6)) = o4;
            }
        }
    }
}

extern "C" void kernel_launch(void* const* d_in, const int* in_sizes, int n_in,
                              void* d_out, int out_size) {
    const float* in      = (const float*)d_in[0];  // (2048,1,64,64) fp32
    const float* w       = (const float*)d_in[1];  // (1,9) fp32
    const float* wf      = (const float*)d_in[2];  // (1,) fp32
    const float* scale_p = (const float*)d_in[3];  // (1,1) fp32
    float* out = (float*)d_out;                    // (1,2048,1,64,64) fp32
    (void)in_sizes; (void)n_in; (void)out_size;

    sobel_norm_kernel<<<GRID, 256>>>(in, w, wf, scale_p, out);
}

// round 16
// speedup vs baseline: 1.2604x; 1.1032x over previous
#include <cuda_runtime.h>
#include <cuda_bf16.h>

// 1 CTA per 64x64 image, 128 threads, single launch.
// Thread t: col quad q=t&15 (cols 4q..4q+3), row block rb=t>>4 (rows 8rb..8rb+7).
// TALL TILE (4x8): 10 row loads per thread for 8 output rows (1.25x read amp),
// 10 expands per 32 px (vs 6 per 16 px before) -> ~20% fewer issues per pixel.
// Loads staged: 6 front-issued, 4 more issued after first conv row.
// Halo via warp shuffle; per-warp coeffs (lanes 0-8, shfl broadcast).
// |gx|+|gy| == max(|conv(S)|, |conv(D)|), S=wr+wr^T, D=wr-wr^T.
// Warp min/max via redux.sync.u32 on float bits (g >= 0); cross-warp smem atomics.

#define FULL 0xffffffffu
#define NUM_IMG 2048

__global__ __launch_bounds__(128)
void sobel_norm_kernel(const float* __restrict__ in,
                       const float* __restrict__ w,
                       const float* __restrict__ wf,
                       const float* __restrict__ scale_p,
                       float* __restrict__ out) {
    __shared__ unsigned s_mn, s_mx;

    const int tid  = threadIdx.x;
    const int lane = tid & 31;
    const int q    = tid & 15;        // col quad 0..15
    const int rb   = tid >> 4;        // row block 0..7
    const int r0   = rb << 3;         // first output row (0..56)
    const int c0   = q << 2;

    if (tid == 0) { s_mn = 0x7f800000u; s_mx = 0u; }
    __syncthreads();

    const float* __restrict__ base = in + (size_t)blockIdx.x * 4096 + (r0 << 6) + c0;

    // ---- Front-issue first 6 row loads: rows r0-1 .. r0+4 (MLP=6) ----
    const float4 Z4 = make_float4(0.f, 0.f, 0.f, 0.f);
    const float4 mA = (rb != 0) ? *reinterpret_cast<const float4*>(base - 64) : Z4;
    const float4 mB = *reinterpret_cast<const float4*>(base);
    const float4 mC = *reinterpret_cast<const float4*>(base + 64);
    const float4 mD = *reinterpret_cast<const float4*>(base + 128);
    const float4 mE = *reinterpret_cast<const float4*>(base + 192);
    const float4 mF = *reinterpret_cast<const float4*>(base + 256);

    // ---- Per-warp coefficients (no barrier), hidden under loads ----
    float wv = 0.f;
    if (lane < 9) {
        const float f = fminf(fmaxf(__ldg(wf), 1.0f), 255.0f);
        wv = fminf(fmaxf(__ldg(w + lane), -1.0f), 1.0f) * f;
    }
    const float w0 = __shfl_sync(FULL, wv, 0);
    const float w1 = __shfl_sync(FULL, wv, 1);
    const float w2 = __shfl_sync(FULL, wv, 2);
    const float w3 = __shfl_sync(FULL, wv, 3);
    const float w4 = __shfl_sync(FULL, wv, 4);
    const float w5 = __shfl_sync(FULL, wv, 5);
    const float w6 = __shfl_sync(FULL, wv, 6);
    const float w7 = __shfl_sync(FULL, wv, 7);
    const float w8 = __shfl_sync(FULL, wv, 8);

    const float s00 = w0 + w0, s11 = w4 + w4, s22 = w8 + w8;
    const float s01 = w1 + w3, s02 = w2 + w6, s12 = w5 + w7;
    const float d01 = w1 - w3, d02 = w2 - w6, d12 = w5 - w7;

    auto expand = [&](float4 m, float* V) {
        float lf = __shfl_up_sync(FULL, m.w, 1);
        float rg = __shfl_down_sync(FULL, m.x, 1);
        if (q == 0)  lf = 0.f;
        if (q == 15) rg = 0.f;
        V[0] = lf;
        V[1] = m.x; V[2] = m.y; V[3] = m.z; V[4] = m.w;
        V[5] = rg;
    };

    float g[32];
    float gmn = 3.4e38f;
    float gmx = 0.0f;   // g >= 0
    float W[3][6];

    auto conv4 = [&](const float* a, const float* b, const float* c, float* go) {
#pragma unroll
        for (int p = 0; p < 4; p++) {
            const float a0 = a[p], a1 = a[p + 1], a2 = a[p + 2];
            const float b0 = b[p], b1 = b[p + 1], b2 = b[p + 2];
            const float c1 = c[p], c2 = c[p + 1], c3 = c[p + 2];
            float S = s00 * a0;
            S = fmaf(s11, b1, S);
            S = fmaf(s22, c3, S);
            S = fmaf(s01, a1 + b0, S);
            S = fmaf(s02, a2 + c1, S);
            S = fmaf(s12, b2 + c2, S);
            float D = d01 * (a1 - b0);
            D = fmaf(d02, a2 - c1, D);
            D = fmaf(d12, b2 - c2, D);
            const float gv = fmaxf(fabsf(S), fabsf(D));
            go[p] = gv;
            gmn = fminf(gmn, gv);
            gmx = fmaxf(gmx, gv);
        }
    };

    // ---- First half: output rows 0..3 ----
    expand(mA, W[0]);
    expand(mB, W[1]);
    expand(mC, W[2]);
    conv4(W[0], W[1], W[2], g + 0);

    // Issue second-half loads now (rows r0+5..r0+8); latency covered by 3 conv4s
    const float4 mG = *reinterpret_cast<const float4*>(base + 320);
    const float4 mH = *reinterpret_cast<const float4*>(base + 384);
    const float4 mI = *reinterpret_cast<const float4*>(base + 448);
    const float4 mJ = (rb != 7) ? *reinterpret_cast<const float4*>(base + 512) : Z4;

    expand(mD, W[0]);
    conv4(W[1], W[2], W[0], g + 4);

    expand(mE, W[1]);
    conv4(W[2], W[0], W[1], g + 8);

    expand(mF, W[2]);
    conv4(W[0], W[1], W[2], g + 12);

    // ---- Second half: output rows 4..7 ----
    expand(mG, W[0]);
    conv4(W[1], W[2], W[0], g + 16);

    expand(mH, W[1]);
    conv4(W[2], W[0], W[1], g + 20);

    expand(mI, W[2]);
    conv4(W[0], W[1], W[2], g + 24);

    expand(mJ, W[0]);
    conv4(W[1], W[2], W[0], g + 28);

    // ---- warp reduction: integer redux on float bits (all g >= 0) ----
    unsigned wmn_u, wmx_u;
    asm("redux.sync.min.u32 %0, %1, 0xffffffff;" : "=r"(wmn_u) : "r"(__float_as_uint(gmn)));
    asm("redux.sync.max.u32 %0, %1, 0xffffffff;" : "=r"(wmx_u) : "r"(__float_as_uint(gmx)));
    if (lane == 0) {
        atomicMin(&s_mn, wmn_u);
        atomicMax(&s_mx, wmx_u);
    }
    __syncthreads();

    gmn = __uint_as_float(s_mn);
    gmx = __uint_as_float(s_mx);

    const float mul = 255.0f / fmaxf(gmx - gmn, 1.0f);
    const float nb  = -gmn * mul;
    const float sc  = __ldg(scale_p);

    // ---- normalize + floor (+scale); 8x float4 stores ----
    float* __restrict__ op = out + (size_t)blockIdx.x * 4096 + (r0 << 6) + c0;
    if (sc == 1.0f) {
#pragma unroll
        for (int i = 0; i < 8; i++) {
            float4 o4;
            o4.x = floorf(fmaf(g[i * 4 + 0], mul, nb));
            o4.y = floorf(fmaf(g[i * 4 + 1], mul, nb));
            o4.z = floorf(fmaf(g[i * 4 + 2], mul, nb));
            o4.w = floorf(fmaf(g[i * 4 + 3], mul, nb));
            *reinterpret_cast<float4*>(op + (i << 6)) = o4;
        }
    } else {
        const float isc = 1.0f / sc;
#pragma unroll
        for (int i = 0; i < 8; i++) {
            float4 o4;
            o4.x = floorf(fmaf(g[i * 4 + 0], mul, nb)) * isc;
            o4.y = floorf(fmaf(g[i * 4 + 1], mul, nb)) * isc;
            o4.z = floorf(fmaf(g[i * 4 + 2], mul, nb)) * isc;
            o4.w = floorf(fmaf(g[i * 4 + 3], mul, nb)) * isc;
            *reinterpret_cast<float4*>(op + (i << 6)) = o4;
        }
    }
}

extern "C" void kernel_launch(void* const* d_in, const int* in_sizes, int n_in,
                              void* d_out, int out_size) {
    const float* in      = (const float*)d_in[0];  // (2048,1,64,64) fp32
    const float* w       = (const float*)d_in[1];  // (1,9) fp32
    const float* wf      = (const float*)d_in[2];  // (1,) fp32
    const float* scale_p = (const float*)d_in[3];  // (1,1) fp32
    float* out = (float*)d_out;                    // (1,2048,1,64,64) fp32
    (void)in_sizes; (void)n_in; (void)out_size;

    sobel_norm_kernel<<<NUM_IMG, 128>>>(in, w, wf, scale_p, out);
}

// round 17
// speedup vs baseline: 1.2635x; 1.0025x over previous
#include <cuda_runtime.h>
#include <cuda_bf16.h>

// 1 CTA per 64x64 image, 128 threads, single launch.
// Thread t: col quad q=t&15 (cols 4q..4q+3), row block rb=t>>4 (rows 8rb..8rb+7).
// TALL TILE (4x8). Loads in THREE groups (4/3/3 rows), each consumed promptly,
// to cut peak live float4 registers (R16 held 7 -> 64 regs, occ 43%).
// Halo via warp shuffle; per-warp coeffs (lanes 0-8, shfl broadcast).
// |gx|+|gy| == max(|conv(S)|, |conv(D)|), S=wr+wr^T, D=wr-wr^T.
// Warp min/max via redux.sync.u32 on float bits (g >= 0); cross-warp smem atomics.

#define FULL 0xffffffffu
#define NUM_IMG 2048

__global__ __launch_bounds__(128)
void sobel_norm_kernel(const float* __restrict__ in,
                       const float* __restrict__ w,
                       const float* __restrict__ wf,
                       const float* __restrict__ scale_p,
                       float* __restrict__ out) {
    __shared__ unsigned s_mn, s_mx;

    const int tid  = threadIdx.x;
    const int lane = tid & 31;
    const int q    = tid & 15;        // col quad 0..15
    const int rb   = tid >> 4;        // row block 0..7
    const int r0   = rb << 3;         // first output row (0..56)
    const int c0   = q << 2;

    if (tid == 0) { s_mn = 0x7f800000u; s_mx = 0u; }
    __syncthreads();

    const float* __restrict__ base = in + (size_t)blockIdx.x * 4096 + (r0 << 6) + c0;
    const float4 Z4 = make_float4(0.f, 0.f, 0.f, 0.f);

    // ---- Group 1: rows r0-1 .. r0+2 (4 loads) ----
    float4 mA = (rb != 0) ? *reinterpret_cast<const float4*>(base - 64) : Z4;
    float4 mB = *reinterpret_cast<const float4*>(base);
    float4 mC = *reinterpret_cast<const float4*>(base + 64);
    float4 mD = *reinterpret_cast<const float4*>(base + 128);

    // ---- Per-warp coefficients (no barrier), hidden under group-1 loads ----
    float wv = 0.f;
    if (lane < 9) {
        const float f = fminf(fmaxf(__ldg(wf), 1.0f), 255.0f);
        wv = fminf(fmaxf(__ldg(w + lane), -1.0f), 1.0f) * f;
    }
    const float w0 = __shfl_sync(FULL, wv, 0);
    const float w1 = __shfl_sync(FULL, wv, 1);
    const float w2 = __shfl_sync(FULL, wv, 2);
    const float w3 = __shfl_sync(FULL, wv, 3);
    const float w4 = __shfl_sync(FULL, wv, 4);
    const float w5 = __shfl_sync(FULL, wv, 5);
    const float w6 = __shfl_sync(FULL, wv, 6);
    const float w7 = __shfl_sync(FULL, wv, 7);
    const float w8 = __shfl_sync(FULL, wv, 8);

    const float s00 = w0 + w0, s11 = w4 + w4, s22 = w8 + w8;
    const float s01 = w1 + w3, s02 = w2 + w6, s12 = w5 + w7;
    const float d01 = w1 - w3, d02 = w2 - w6, d12 = w5 - w7;

    auto expand = [&](float4 m, float* V) {
        float lf = __shfl_up_sync(FULL, m.w, 1);
        float rg = __shfl_down_sync(FULL, m.x, 1);
        if (q == 0)  lf = 0.f;
        if (q == 15) rg = 0.f;
        V[0] = lf;
        V[1] = m.x; V[2] = m.y; V[3] = m.z; V[4] = m.w;
        V[5] = rg;
    };

    float g[32];
    float gmn = 3.4e38f;
    float gmx = 0.0f;   // g >= 0
    float W[3][6];

    auto conv4 = [&](const float* a, const float* b, const float* c, float* go) {
#pragma unroll
        for (int p = 0; p < 4; p++) {
            const float a0 = a[p], a1 = a[p + 1], a2 = a[p + 2];
            const float b0 = b[p], b1 = b[p + 1], b2 = b[p + 2];
            const float c1 = c[p], c2 = c[p + 1], c3 = c[p + 2];
            float S = s00 * a0;
            S = fmaf(s11, b1, S);
            S = fmaf(s22, c3, S);
            S = fmaf(s01, a1 + b0, S);
            S = fmaf(s02, a2 + c1, S);
            S = fmaf(s12, b2 + c2, S);
            float D = d01 * (a1 - b0);
            D = fmaf(d02, a2 - c1, D);
            D = fmaf(d12, b2 - c2, D);
            const float gv = fmaxf(fabsf(S), fabsf(D));
            go[p] = gv;
            gmn = fminf(gmn, gv);
            gmx = fmaxf(gmx, gv);
        }
    };

    // ---- Group 2 loads (rows r0+3..r0+5), then consume group 1 ----
    float4 mE = *reinterpret_cast<const float4*>(base + 192);
    float4 mF = *reinterpret_cast<const float4*>(base + 256);
    float4 mG = *reinterpret_cast<const float4*>(base + 320);

    expand(mA, W[0]);
    expand(mB, W[1]);
    expand(mC, W[2]);
    conv4(W[0], W[1], W[2], g + 0);       // out row 0

    expand(mD, W[0]);
    conv4(W[1], W[2], W[0], g + 4);       // out row 1

    // ---- Group 3 loads (rows r0+6..r0+8), then consume group 2 ----
    float4 mH = *reinterpret_cast<const float4*>(base + 384);
    float4 mI = *reinterpret_cast<const float4*>(base + 448);
    float4 mJ = (rb != 7) ? *reinterpret_cast<const float4*>(base + 512) : Z4;

    expand(mE, W[1]);
    conv4(W[2], W[0], W[1], g + 8);       // out row 2

    expand(mF, W[2]);
    conv4(W[0], W[1], W[2], g + 12);      // out row 3

    expand(mG, W[0]);
    conv4(W[1], W[2], W[0], g + 16);      // out row 4

    expand(mH, W[1]);
    conv4(W[2], W[0], W[1], g + 20);      // out row 5

    expand(mI, W[2]);
    conv4(W[0], W[1], W[2], g + 24);      // out row 6

    expand(mJ, W[0]);
    conv4(W[1], W[2], W[0], g + 28);      // out row 7

    // ---- warp reduction: integer redux on float bits (all g >= 0) ----
    unsigned wmn_u, wmx_u;
    asm("redux.sync.min.u32 %0, %1, 0xffffffff;" : "=r"(wmn_u) : "r"(__float_as_uint(gmn)));
    asm("redux.sync.max.u32 %0, %1, 0xffffffff;" : "=r"(wmx_u) : "r"(__float_as_uint(gmx)));
    if (lane == 0) {
        atomicMin(&s_mn, wmn_u);
        atomicMax(&s_mx, wmx_u);
    }
    __syncthreads();

    gmn = __uint_as_float(s_mn);
    gmx = __uint_as_float(s_mx);

    const float mul = 255.0f / fmaxf(gmx - gmn, 1.0f);
    const float nb  = -gmn * mul;
    const float sc  = __ldg(scale_p);

    // ---- normalize + floor (+scale); 8x float4 stores ----
    float* __restrict__ op = out + (size_t)blockIdx.x * 4096 + (r0 << 6) + c0;
    if (sc == 1.0f) {
#pragma unroll
        for (int i = 0; i < 8; i++) {
            float4 o4;
            o4.x = floorf(fmaf(g[i * 4 + 0], mul, nb));
            o4.y = floorf(fmaf(g[i * 4 + 1], mul, nb));
            o4.z = floorf(fmaf(g[i * 4 + 2], mul, nb));
            o4.w = floorf(fmaf(g[i * 4 + 3], mul, nb));
            *reinterpret_cast<float4*>(op + (i << 6)) = o4;
        }
    } else {
        const float isc = 1.0f / sc;
#pragma unroll
        for (int i = 0; i < 8; i++) {
            float4 o4;
            o4.x = floorf(fmaf(g[i * 4 + 0], mul, nb)) * isc;
            o4.y = floorf(fmaf(g[i * 4 + 1], mul, nb)) * isc;
            o4.z = floorf(fmaf(g[i * 4 + 2], mul, nb)) * isc;
            o4.w = floorf(fmaf(g[i * 4 + 3], mul, nb)) * isc;
            *reinterpret_cast<float4*>(op + (i << 6)) = o4;
        }
    }
}

extern "C" void kernel_launch(void* const* d_in, const int* in_sizes, int n_in,
                              void* d_out, int out_size) {
    const float* in      = (const float*)d_in[0];  // (2048,1,64,64) fp32
    const float* w       = (const float*)d_in[1];  // (1,9) fp32
    const float* wf      = (const float*)d_in[2];  // (1,) fp32
    const float* scale_p = (const float*)d_in[3];  // (1,1) fp32
    float* out = (float*)d_out;                    // (1,2048,1,64,64) fp32
    (void)in_sizes; (void)n_in; (void)out_size;

    sobel_norm_kernel<<<NUM_IMG, 128>>>(in, w, wf, scale_p, out);
}